// round 1
// baseline (speedup 1.0000x reference)
#include <cuda_runtime.h>

#define BSZ 128
#define KTOT 196608
#define NCHUNK 512
#define KC 384            // NCHUNK * KC == KTOT
#define KT 32
#define REGC 0.01f
#define LOGAB -4.852030263919617f   // log(1/128)

// Scratch (static device arrays: no allocation anywhere)
__device__ float g_partC[(size_t)NCHUNK * BSZ * BSZ];   // 32 MB partial GEMM sums
__device__ float g_partX2[NCHUNK * BSZ];
__device__ float g_partY2[NCHUNK * BSZ];
__device__ float g_C[BSZ * BSZ];

// ---------------------------------------------------------------------------
// Stage A: split-K partial GEMM  partial[chunk][i][j] = sum_k delta[i,k]*tgt[j,k]
// delta computed on the fly (imgs_w - imgs). Also partial row/col sq-norms.
// 256 threads, 8x8 register micro-tiles, 128x128 output tile per CTA.
// ---------------------------------------------------------------------------
__global__ __launch_bounds__(256, 2) void gemm_part_kernel(
    const float* __restrict__ imgs,
    const float* __restrict__ imgsw,
    const float* __restrict__ tgt)
{
    __shared__ float As[KT][BSZ + 1];   // +1 pad: conflict-free transposed stores
    __shared__ float Bs[KT][BSZ + 1];

    const int chunk = blockIdx.x;
    const int k0 = chunk * KC;
    const int t = threadIdx.x;
    const int tx = t & 15;        // 0..15  -> 8 output cols
    const int ty = t >> 4;        // 0..15  -> 8 output rows
    const int lr = t >> 3;        // 0..31  loader row-in-pass
    const int lk = (t & 7) << 2;  // 0,4,...,28 loader k offset (float4)

    float acc[8][8];
#pragma unroll
    for (int r = 0; r < 8; r++)
#pragma unroll
        for (int c = 0; c < 8; c++) acc[r][c] = 0.0f;

    float ax2[4] = {0.f, 0.f, 0.f, 0.f};
    float by2[4] = {0.f, 0.f, 0.f, 0.f};

    for (int kt = 0; kt < KC; kt += KT) {
#pragma unroll
        for (int p = 0; p < 4; p++) {
            const int r = p * 32 + lr;
            const size_t gi = (size_t)r * KTOT + (size_t)(k0 + kt + lk);
            const float4 aw = *(const float4*)(imgsw + gi);
            const float4 a0 = *(const float4*)(imgs + gi);
            const float4 bb = *(const float4*)(tgt + gi);
            const float d0 = aw.x - a0.x;
            const float d1 = aw.y - a0.y;
            const float d2 = aw.z - a0.z;
            const float d3 = aw.w - a0.w;
            As[lk + 0][r] = d0; As[lk + 1][r] = d1;
            As[lk + 2][r] = d2; As[lk + 3][r] = d3;
            Bs[lk + 0][r] = bb.x; Bs[lk + 1][r] = bb.y;
            Bs[lk + 2][r] = bb.z; Bs[lk + 3][r] = bb.w;
            ax2[p] += d0 * d0 + d1 * d1 + d2 * d2 + d3 * d3;
            by2[p] += bb.x * bb.x + bb.y * bb.y + bb.z * bb.z + bb.w * bb.w;
        }
        __syncthreads();

#pragma unroll 4
        for (int kk = 0; kk < KT; kk++) {
            float a[8], b[8];
#pragma unroll
            for (int r = 0; r < 8; r++) a[r] = As[kk][ty * 8 + r];
#pragma unroll
            for (int c = 0; c < 8; c++) b[c] = Bs[kk][tx * 8 + c];
#pragma unroll
            for (int r = 0; r < 8; r++)
#pragma unroll
                for (int c = 0; c < 8; c++)
                    acc[r][c] = fmaf(a[r], b[c], acc[r][c]);
        }
        __syncthreads();
    }

    // write partial C tile (deterministic: one writer per slot)
    float* outp = &g_partC[(size_t)chunk * BSZ * BSZ];
#pragma unroll
    for (int r = 0; r < 8; r++)
#pragma unroll
        for (int c = 0; c < 8; c++)
            outp[(ty * 8 + r) * BSZ + tx * 8 + c] = acc[r][c];

    // reduce norms over the 8 lanes that share a loader row
#pragma unroll
    for (int d = 1; d < 8; d <<= 1) {
#pragma unroll
        for (int p = 0; p < 4; p++) {
            ax2[p] += __shfl_xor_sync(0xffffffffu, ax2[p], d);
            by2[p] += __shfl_xor_sync(0xffffffffu, by2[p], d);
        }
    }
    if ((t & 7) == 0) {
#pragma unroll
        for (int p = 0; p < 4; p++) {
            g_partX2[chunk * BSZ + p * 32 + lr] = ax2[p];
            g_partY2[chunk * BSZ + p * 32 + lr] = by2[p];
        }
    }
}

// ---------------------------------------------------------------------------
// Stage B: deterministic reduction over chunks  ->  C = sqrt(max(x2+y2-2xy,0))
// ---------------------------------------------------------------------------
__global__ void assemble_kernel()
{
    const int i = blockIdx.x;
    const int j = threadIdx.x;
    float s = 0.f, x2 = 0.f, y2 = 0.f;
#pragma unroll 4
    for (int c = 0; c < NCHUNK; c++) {
        s  += g_partC[(size_t)c * BSZ * BSZ + i * BSZ + j];
        x2 += g_partX2[c * BSZ + i];
        y2 += g_partY2[c * BSZ + j];
    }
    const float sq = fmaxf(x2 + y2 - 2.0f * s, 0.0f);
    g_C[i * BSZ + j] = sqrtf(sq);
}

// ---------------------------------------------------------------------------
// Stage C: Sinkhorn (100 iters) in ONE CTA of 1024 threads.
// Restructured:  LSE_row_i = -u_i + M_i + log( sum_j exp(C_ij - M_i) e^{-v_j} )
// P = exp(C - rowmax) kept row-major in registers (16/thread),
// Q = exp(C - colmax) kept col-major in registers. Each iteration is two
// register-resident 128x128 GEMVs -> no per-iteration matrix exp.
// ---------------------------------------------------------------------------
__global__ __launch_bounds__(1024, 1) void sinkhorn_kernel(float* __restrict__ out)
{
    __shared__ float w_s[BSZ];    // exp(-v_j)
    __shared__ float wu_s[BSZ];   // exp(-u_i)
    __shared__ float u_fin[BSZ];
    __shared__ float v_fin[BSZ];

    const int t = threadIdx.x;
    const int r8 = t >> 3;        // row (phase 1) / col (phase 2), 0..127
    const int g = t & 7;          // 8 lanes cooperate per row/col
    const int off = g << 4;       // 16-element segment

    float p[16], q[16];
    float M_i, N_j;

    // row segment + rowmax -> P
    {
        float m = -3.0e38f;
#pragma unroll
        for (int k = 0; k < 16; k++) {
            p[k] = g_C[r8 * BSZ + off + k];
            m = fmaxf(m, p[k]);
        }
#pragma unroll
        for (int d = 1; d < 8; d <<= 1)
            m = fmaxf(m, __shfl_xor_sync(0xffffffffu, m, d));
        M_i = m;
#pragma unroll
        for (int k = 0; k < 16; k++) p[k] = __expf(p[k] - m);
    }
    // column segment + colmax -> Q
    {
        float n = -3.0e38f;
#pragma unroll
        for (int k = 0; k < 16; k++) {
            q[k] = g_C[(off + k) * BSZ + r8];
            n = fmaxf(n, q[k]);
        }
#pragma unroll
        for (int d = 1; d < 8; d <<= 1)
            n = fmaxf(n, __shfl_xor_sync(0xffffffffu, n, d));
        N_j = n;
#pragma unroll
        for (int k = 0; k < 16; k++) q[k] = __expf(q[k] - n);
    }

    float u_i = 0.0f, v_j = 0.0f;
    if (t < BSZ) { w_s[t] = 1.0f; wu_s[t] = 1.0f; }   // u0 = v0 = 0
    __syncthreads();

    for (int it = 0; it < 100; it++) {
        // ---- phase 1: u update (uses w = exp(-v)) ----
        float s0 = 0.f, s1 = 0.f, s2 = 0.f, s3 = 0.f;
#pragma unroll
        for (int k = 0; k < 16; k += 4) {
            s0 = fmaf(p[k + 0], w_s[off + k + 0], s0);
            s1 = fmaf(p[k + 1], w_s[off + k + 1], s1);
            s2 = fmaf(p[k + 2], w_s[off + k + 2], s2);
            s3 = fmaf(p[k + 3], w_s[off + k + 3], s3);
        }
        float s = (s0 + s1) + (s2 + s3);
        s += __shfl_xor_sync(0xffffffffu, s, 1);
        s += __shfl_xor_sync(0xffffffffu, s, 2);
        s += __shfl_xor_sync(0xffffffffu, s, 4);
        if (g == 0) {
            u_i = REGC * (LOGAB + u_i - M_i - __logf(s));
            wu_s[r8] = __expf(-u_i);
        }
        __syncthreads();

        // ---- phase 2: v update (uses new u) ----
        float t0 = 0.f, t1 = 0.f, t2 = 0.f, t3 = 0.f;
#pragma unroll
        for (int k = 0; k < 16; k += 4) {
            t0 = fmaf(q[k + 0], wu_s[off + k + 0], t0);
            t1 = fmaf(q[k + 1], wu_s[off + k + 1], t1);
            t2 = fmaf(q[k + 2], wu_s[off + k + 2], t2);
            t3 = fmaf(q[k + 3], wu_s[off + k + 3], t3);
        }
        float tt = (t0 + t1) + (t2 + t3);
        tt += __shfl_xor_sync(0xffffffffu, tt, 1);
        tt += __shfl_xor_sync(0xffffffffu, tt, 2);
        tt += __shfl_xor_sync(0xffffffffu, tt, 4);
        if (g == 0) {
            v_j = REGC * (LOGAB + v_j - N_j - __logf(tt));
            w_s[r8] = __expf(-v_j);
        }
        __syncthreads();
    }

    if (g == 0) { u_fin[r8] = u_i; v_fin[r8] = v_j; }
    __syncthreads();
    if (t == 0) {
        float acc = 0.0f;
        for (int i = 0; i < BSZ; i++) acc += u_fin[i] + v_fin[i];
        out[0] = acc * (1.0f / 128.0f);   // sum(u*a + v*b), a=b=1/128
    }
}

// ---------------------------------------------------------------------------
extern "C" void kernel_launch(void* const* d_in, const int* in_sizes, int n_in,
                              void* d_out, int out_size)
{
    const float* imgs  = (const float*)d_in[0];
    const float* imgsw = (const float*)d_in[1];
    const float* tgt   = (const float*)d_in[2];

    gemm_part_kernel<<<NCHUNK, 256>>>(imgs, imgsw, tgt);
    assemble_kernel<<<BSZ, BSZ>>>();
    sinkhorn_kernel<<<1, 1024>>>((float*)d_out);
}

// round 5
// speedup vs baseline: 1.5970x; 1.5970x over previous
#include <cuda_runtime.h>
#include <cuda_bf16.h>
#include <cstdint>

#define BSZ 128
#define KTOT 196608
#define NCHUNK 256
#define KC 768            // NCHUNK * KC == KTOT
#define KT 64             // k per smem stage
#define SA 72             // smem row stride in bf16 (KT + 8 pad, conflict-free)
#define REGC 0.01f
#define LOGAB -4.852030263919617f   // log(1/128)

// Scratch (static device arrays: no allocation anywhere)
__device__ float g_partC[(size_t)NCHUNK * BSZ * BSZ];   // 16 MB partial GEMM sums
__device__ float g_partX2[NCHUNK * BSZ];
__device__ float g_partY2[NCHUNK * BSZ];
__device__ float g_C[BSZ * BSZ];

// mma.sync m16n8k16 bf16 -> f32, accumulate in place
__device__ __forceinline__ void mma_bf16(float& c0, float& c1, float& c2, float& c3,
                                         uint32_t a0, uint32_t a1, uint32_t a2, uint32_t a3,
                                         uint32_t b0, uint32_t b1)
{
    asm volatile(
        "mma.sync.aligned.m16n8k16.row.col.f32.bf16.bf16.f32 "
        "{%0,%1,%2,%3}, {%4,%5,%6,%7}, {%8,%9}, {%0,%1,%2,%3};\n"
        : "+f"(c0), "+f"(c1), "+f"(c2), "+f"(c3)
        : "r"(a0), "r"(a1), "r"(a2), "r"(a3), "r"(b0), "r"(b1));
}

// ---------------------------------------------------------------------------
// Stage A: split-K partial GEMM on tensor cores (bf16 HMMA via inline PTX).
// partial[chunk][i][j] = sum_k delta[i,k]*tgt[j,k], delta = imgs_w - imgs.
// Norms accumulated in fp32 during staging. 256 threads, 8 warps,
// warp tile 32x64 = 2x8 mma tiles of 16x8 (k-step 16).
// ---------------------------------------------------------------------------
__global__ __launch_bounds__(256, 2) void gemm_part_kernel(
    const float* __restrict__ imgs,
    const float* __restrict__ imgsw,
    const float* __restrict__ tgt)
{
    __shared__ __nv_bfloat16 As[BSZ][SA];
    __shared__ __nv_bfloat16 Bs[BSZ][SA];

    const int chunk = blockIdx.x;
    const int k0 = chunk * KC;
    const int t = threadIdx.x;
    const int warp = t >> 5;
    const int lane = t & 31;
    const int gid = lane >> 2;        // group 0..7
    const int tig = lane & 3;         // thread-in-group 0..3
    const int wr = warp & 3;          // warp row block (32 rows)
    const int wc = warp >> 2;         // warp col block (64 cols)

    // Loader mapping: 2 threads per row, interleaved float4s (perfect coalescing)
    const int lrow = t >> 1;          // 0..127
    const int lh = t & 1;             // float4 parity

    float c[2][8][4];
#pragma unroll
    for (int i = 0; i < 2; i++)
#pragma unroll
        for (int j = 0; j < 8; j++)
#pragma unroll
            for (int r = 0; r < 4; r++) c[i][j][r] = 0.0f;

    float ax2 = 0.0f, by2 = 0.0f;

    for (int kt = 0; kt < KC; kt += KT) {
        __syncthreads();   // previous stage's MMA reads done
#pragma unroll
        for (int i = 0; i < 8; i++) {
            const int kk = (lh + 2 * i) * 4;                  // 0..60, float offset in tile
            const size_t gi = (size_t)lrow * KTOT + (size_t)(k0 + kt + kk);
            const float4 aw = *(const float4*)(imgsw + gi);
            const float4 a0 = *(const float4*)(imgs + gi);
            const float4 bb = *(const float4*)(tgt + gi);
            const float d0 = aw.x - a0.x;
            const float d1 = aw.y - a0.y;
            const float d2 = aw.z - a0.z;
            const float d3 = aw.w - a0.w;
            ax2 += d0 * d0 + d1 * d1 + d2 * d2 + d3 * d3;
            by2 += bb.x * bb.x + bb.y * bb.y + bb.z * bb.z + bb.w * bb.w;

            *(__nv_bfloat162*)&As[lrow][kk + 0] = __floats2bfloat162_rn(d0, d1);
            *(__nv_bfloat162*)&As[lrow][kk + 2] = __floats2bfloat162_rn(d2, d3);
            *(__nv_bfloat162*)&Bs[lrow][kk + 0] = __floats2bfloat162_rn(bb.x, bb.y);
            *(__nv_bfloat162*)&Bs[lrow][kk + 2] = __floats2bfloat162_rn(bb.z, bb.w);
        }
        __syncthreads();

#pragma unroll
        for (int ks = 0; ks < KT / 16; ks++) {
            const int kb = ks * 16;
            // A fragments: two 16x16 row-major tiles
            uint32_t af[2][4];
#pragma unroll
            for (int i = 0; i < 2; i++) {
                const int r0 = wr * 32 + i * 16 + gid;
                af[i][0] = *(const uint32_t*)&As[r0    ][kb + 2 * tig    ];
                af[i][1] = *(const uint32_t*)&As[r0 + 8][kb + 2 * tig    ];
                af[i][2] = *(const uint32_t*)&As[r0    ][kb + 2 * tig + 8];
                af[i][3] = *(const uint32_t*)&As[r0 + 8][kb + 2 * tig + 8];
            }
            // B fragments: eight 16x8 col-major tiles (Bs[j][k] is k-contiguous)
            uint32_t bf[8][2];
#pragma unroll
            for (int j = 0; j < 8; j++) {
                const int col = wc * 64 + j * 8 + gid;
                bf[j][0] = *(const uint32_t*)&Bs[col][kb + 2 * tig    ];
                bf[j][1] = *(const uint32_t*)&Bs[col][kb + 2 * tig + 8];
            }
#pragma unroll
            for (int i = 0; i < 2; i++)
#pragma unroll
                for (int j = 0; j < 8; j++)
                    mma_bf16(c[i][j][0], c[i][j][1], c[i][j][2], c[i][j][3],
                             af[i][0], af[i][1], af[i][2], af[i][3],
                             bf[j][0], bf[j][1]);
        }
    }

    // write partial C tile (deterministic, one writer per slot)
    float* outp = &g_partC[(size_t)chunk * BSZ * BSZ];
#pragma unroll
    for (int i = 0; i < 2; i++) {
        const int r0 = wr * 32 + i * 16 + gid;
#pragma unroll
        for (int j = 0; j < 8; j++) {
            const int col = wc * 64 + j * 8 + 2 * tig;
            *(float2*)&outp[r0 * BSZ + col]       = make_float2(c[i][j][0], c[i][j][1]);
            *(float2*)&outp[(r0 + 8) * BSZ + col] = make_float2(c[i][j][2], c[i][j][3]);
        }
    }

    // norms: 2 threads per row -> pairwise shfl reduce, lh==0 writes
    ax2 += __shfl_xor_sync(0xffffffffu, ax2, 1);
    by2 += __shfl_xor_sync(0xffffffffu, by2, 1);
    if (lh == 0) {
        g_partX2[chunk * BSZ + lrow] = ax2;
        g_partY2[chunk * BSZ + lrow] = by2;
    }
}

// ---------------------------------------------------------------------------
// Stage B: deterministic reduction over chunks  ->  C = sqrt(max(x2+y2-2xy,0))
// ---------------------------------------------------------------------------
__global__ void assemble_kernel()
{
    const int i = blockIdx.x;
    const int j = threadIdx.x;
    float s = 0.f, x2 = 0.f, y2 = 0.f;
#pragma unroll 8
    for (int c = 0; c < NCHUNK; c++) {
        s  += g_partC[(size_t)c * BSZ * BSZ + i * BSZ + j];
        x2 += g_partX2[c * BSZ + i];
        y2 += g_partY2[c * BSZ + j];
    }
    const float sq = fmaxf(x2 + y2 - 2.0f * s, 0.0f);
    g_C[i * BSZ + j] = sqrtf(sq);
}

// ---------------------------------------------------------------------------
// Stage C: Sinkhorn (100 iters) in ONE CTA of 1024 threads.
// P = exp(C - rowmax) row-major in registers, Q = exp(C - colmax) col-major.
// Each iteration = two register-resident 128x128 GEMVs; w vectors read as
// float4 from smem.
// ---------------------------------------------------------------------------
__global__ __launch_bounds__(1024, 1) void sinkhorn_kernel(float* __restrict__ out)
{
    __shared__ __align__(16) float w_s[BSZ];    // exp(-v_j)
    __shared__ __align__(16) float wu_s[BSZ];   // exp(-u_i)
    __shared__ float u_fin[BSZ];
    __shared__ float v_fin[BSZ];

    const int t = threadIdx.x;
    const int r8 = t >> 3;        // row (phase 1) / col (phase 2), 0..127
    const int g = t & 7;          // 8 lanes cooperate per row/col
    const int off = g << 4;       // 16-element segment

    float p[16], q[16];
    float M_i, N_j;

    {
        float m = -3.0e38f;
#pragma unroll
        for (int k = 0; k < 16; k++) {
            p[k] = g_C[r8 * BSZ + off + k];
            m = fmaxf(m, p[k]);
        }
#pragma unroll
        for (int d = 1; d < 8; d <<= 1)
            m = fmaxf(m, __shfl_xor_sync(0xffffffffu, m, d));
        M_i = m;
#pragma unroll
        for (int k = 0; k < 16; k++) p[k] = __expf(p[k] - m);
    }
    {
        float n = -3.0e38f;
#pragma unroll
        for (int k = 0; k < 16; k++) {
            q[k] = g_C[(off + k) * BSZ + r8];
            n = fmaxf(n, q[k]);
        }
#pragma unroll
        for (int d = 1; d < 8; d <<= 1)
            n = fmaxf(n, __shfl_xor_sync(0xffffffffu, n, d));
        N_j = n;
#pragma unroll
        for (int k = 0; k < 16; k++) q[k] = __expf(q[k] - n);
    }

    float u_i = 0.0f, v_j = 0.0f;
    if (t < BSZ) { w_s[t] = 1.0f; wu_s[t] = 1.0f; }   // u0 = v0 = 0
    __syncthreads();

    const float4* w4  = (const float4*)(w_s  + off);
    const float4* wu4 = (const float4*)(wu_s + off);

    for (int it = 0; it < 100; it++) {
        // ---- phase 1: u update ----
        float s0 = 0.f, s1 = 0.f, s2 = 0.f, s3 = 0.f;
#pragma unroll
        for (int k4 = 0; k4 < 4; k4++) {
            const float4 w = w4[k4];
            s0 = fmaf(p[k4 * 4 + 0], w.x, s0);
            s1 = fmaf(p[k4 * 4 + 1], w.y, s1);
            s2 = fmaf(p[k4 * 4 + 2], w.z, s2);
            s3 = fmaf(p[k4 * 4 + 3], w.w, s3);
        }
        float s = (s0 + s1) + (s2 + s3);
        s += __shfl_xor_sync(0xffffffffu, s, 1);
        s += __shfl_xor_sync(0xffffffffu, s, 2);
        s += __shfl_xor_sync(0xffffffffu, s, 4);
        if (g == 0) {
            u_i = REGC * (LOGAB + u_i - M_i - __logf(s));
            wu_s[r8] = __expf(-u_i);
        }
        __syncthreads();

        // ---- phase 2: v update ----
        float t0 = 0.f, t1 = 0.f, t2 = 0.f, t3 = 0.f;
#pragma unroll
        for (int k4 = 0; k4 < 4; k4++) {
            const float4 w = wu4[k4];
            t0 = fmaf(q[k4 * 4 + 0], w.x, t0);
            t1 = fmaf(q[k4 * 4 + 1], w.y, t1);
            t2 = fmaf(q[k4 * 4 + 2], w.z, t2);
            t3 = fmaf(q[k4 * 4 + 3], w.w, t3);
        }
        float tt = (t0 + t1) + (t2 + t3);
        tt += __shfl_xor_sync(0xffffffffu, tt, 1);
        tt += __shfl_xor_sync(0xffffffffu, tt, 2);
        tt += __shfl_xor_sync(0xffffffffu, tt, 4);
        if (g == 0) {
            v_j = REGC * (LOGAB + v_j - N_j - __logf(tt));
            w_s[r8] = __expf(-v_j);
        }
        __syncthreads();
    }

    if (g == 0) { u_fin[r8] = u_i; v_fin[r8] = v_j; }
    __syncthreads();
    if (t == 0) {
        float acc = 0.0f;
        for (int i = 0; i < BSZ; i++) acc += u_fin[i] + v_fin[i];
        out[0] = acc * (1.0f / 128.0f);   // sum(u*a + v*b), a=b=1/128
    }
}

// ---------------------------------------------------------------------------
extern "C" void kernel_launch(void* const* d_in, const int* in_sizes, int n_in,
                              void* d_out, int out_size)
{
    const float* imgs  = (const float*)d_in[0];
    const float* imgsw = (const float*)d_in[1];
    const float* tgt   = (const float*)d_in[2];

    gemm_part_kernel<<<NCHUNK, 256>>>(imgs, imgsw, tgt);
    assemble_kernel<<<BSZ, BSZ>>>();
    sinkhorn_kernel<<<1, 1024>>>((float*)d_out);
}

// round 6
// speedup vs baseline: 1.8073x; 1.1317x over previous
#include <cuda_runtime.h>
#include <cuda_bf16.h>
#include <cstdint>

#define BSZ 128
#define KTOT 196608
#define NCHUNK 128
#define KC 1536           // NCHUNK * KC == KTOT
#define KT 32             // k per smem stage
#define NST (KC / KT)     // 48 stages
#define SA 40             // smem row stride in bf16 (KT + 8 pad)
#define REGC 0.01f
#define LOGAB -4.852030263919617f   // log(1/128)

// Scratch (static device arrays: no allocation anywhere)
__device__ float g_partC[(size_t)NCHUNK * BSZ * BSZ];   // 8 MB partial GEMM sums
__device__ float g_partX2[NCHUNK * BSZ];
__device__ float g_partY2[NCHUNK * BSZ];
__device__ float g_C[BSZ * BSZ];

// mma.sync m16n8k16 bf16 -> f32, accumulate in place
__device__ __forceinline__ void mma_bf16(float* c,
                                         uint32_t a0, uint32_t a1, uint32_t a2, uint32_t a3,
                                         uint32_t b0, uint32_t b1)
{
    asm volatile(
        "mma.sync.aligned.m16n8k16.row.col.f32.bf16.bf16.f32 "
        "{%0,%1,%2,%3}, {%4,%5,%6,%7}, {%8,%9}, {%0,%1,%2,%3};\n"
        : "+f"(c[0]), "+f"(c[1]), "+f"(c[2]), "+f"(c[3])
        : "r"(a0), "r"(a1), "r"(a2), "r"(a3), "r"(b0), "r"(b1));
}

// ---------------------------------------------------------------------------
// Stage A: split-K partial GEMM, bf16 HMMA, 2-stage double-buffered pipeline.
// 512 threads / 16 warps, warp tile 32x32 (2x4 m16n8k16 tiles).
// partial[chunk][i][j] = sum_k delta[i,k]*tgt[j,k], delta = imgs_w - imgs.
// Norms in fp32 on the staging path.
// ---------------------------------------------------------------------------
__global__ __launch_bounds__(512, 1) void gemm_part_kernel(
    const float* __restrict__ imgs,
    const float* __restrict__ imgsw,
    const float* __restrict__ tgt)
{
    __shared__ __nv_bfloat16 As[2][BSZ][SA];
    __shared__ __nv_bfloat16 Bs[2][BSZ][SA];

    const int chunk = blockIdx.x;
    const int k0 = chunk * KC;
    const int t = threadIdx.x;
    const int warp = t >> 5;
    const int lane = t & 31;
    const int gid = lane >> 2;        // 0..7
    const int tig = lane & 3;         // 0..3
    const int wr = warp & 3;          // warp row block (32 rows)
    const int wc = warp >> 2;         // warp col block (32 cols)

    // Loader: 4 threads per row, each loads 2 interleaved float4 per array/stage
    const int lrow = t >> 2;          // 0..127
    const int lq = t & 3;

    float c[2][4][4];
#pragma unroll
    for (int i = 0; i < 2; i++)
#pragma unroll
        for (int j = 0; j < 4; j++)
#pragma unroll
            for (int r = 0; r < 4; r++) c[i][j][r] = 0.0f;

    float ax2 = 0.0f, by2 = 0.0f;

    float4 raw[2], ra0[2], rbb[2];    // prefetch registers (6 float4)

    auto load_stage = [&](int s) {
        const size_t base = (size_t)lrow * KTOT + (size_t)(k0 + s * KT);
#pragma unroll
        for (int i = 0; i < 2; i++) {
            const int kk = (lq + 4 * i) * 4;
            raw[i] = *(const float4*)(imgsw + base + kk);
            ra0[i] = *(const float4*)(imgs  + base + kk);
            rbb[i] = *(const float4*)(tgt   + base + kk);
        }
    };

    auto convert_stage = [&](int buf) {
#pragma unroll
        for (int i = 0; i < 2; i++) {
            const int kk = (lq + 4 * i) * 4;
            const float d0 = raw[i].x - ra0[i].x;
            const float d1 = raw[i].y - ra0[i].y;
            const float d2 = raw[i].z - ra0[i].z;
            const float d3 = raw[i].w - ra0[i].w;
            ax2 += d0 * d0 + d1 * d1 + d2 * d2 + d3 * d3;
            by2 += rbb[i].x * rbb[i].x + rbb[i].y * rbb[i].y
                 + rbb[i].z * rbb[i].z + rbb[i].w * rbb[i].w;
            *(__nv_bfloat162*)&As[buf][lrow][kk + 0] = __floats2bfloat162_rn(d0, d1);
            *(__nv_bfloat162*)&As[buf][lrow][kk + 2] = __floats2bfloat162_rn(d2, d3);
            *(__nv_bfloat162*)&Bs[buf][lrow][kk + 0] = __floats2bfloat162_rn(rbb[i].x, rbb[i].y);
            *(__nv_bfloat162*)&Bs[buf][lrow][kk + 2] = __floats2bfloat162_rn(rbb[i].z, rbb[i].w);
        }
    };

    auto mma_stage = [&](int buf) {
#pragma unroll
        for (int ks = 0; ks < KT / 16; ks++) {
            const int kb = ks * 16;
            uint32_t af[2][4];
#pragma unroll
            for (int i = 0; i < 2; i++) {
                const int r0 = wr * 32 + i * 16 + gid;
                af[i][0] = *(const uint32_t*)&As[buf][r0    ][kb + 2 * tig    ];
                af[i][1] = *(const uint32_t*)&As[buf][r0 + 8][kb + 2 * tig    ];
                af[i][2] = *(const uint32_t*)&As[buf][r0    ][kb + 2 * tig + 8];
                af[i][3] = *(const uint32_t*)&As[buf][r0 + 8][kb + 2 * tig + 8];
            }
            uint32_t bfr[4][2];
#pragma unroll
            for (int j = 0; j < 4; j++) {
                const int col = wc * 32 + j * 8 + gid;
                bfr[j][0] = *(const uint32_t*)&Bs[buf][col][kb + 2 * tig    ];
                bfr[j][1] = *(const uint32_t*)&Bs[buf][col][kb + 2 * tig + 8];
            }
#pragma unroll
            for (int i = 0; i < 2; i++)
#pragma unroll
                for (int j = 0; j < 4; j++)
                    mma_bf16(c[i][j], af[i][0], af[i][1], af[i][2], af[i][3],
                             bfr[j][0], bfr[j][1]);
        }
    };

    // Pipeline: load(s+1) issued before mma(s); convert(s+1) after mma(s)
    load_stage(0);
    convert_stage(0);
    __syncthreads();
    for (int s = 0; s < NST; s++) {
        if (s + 1 < NST) load_stage(s + 1);
        mma_stage(s & 1);
        if (s + 1 < NST) convert_stage((s + 1) & 1);
        __syncthreads();
    }

    // write partial C tile (deterministic, one writer per slot)
    float* outp = &g_partC[(size_t)chunk * BSZ * BSZ];
#pragma unroll
    for (int i = 0; i < 2; i++) {
        const int r0 = wr * 32 + i * 16 + gid;
#pragma unroll
        for (int j = 0; j < 4; j++) {
            const int col = wc * 32 + j * 8 + 2 * tig;
            *(float2*)&outp[r0 * BSZ + col]       = make_float2(c[i][j][0], c[i][j][1]);
            *(float2*)&outp[(r0 + 8) * BSZ + col] = make_float2(c[i][j][2], c[i][j][3]);
        }
    }

    // norms: 4 lanes per row -> shfl reduce, lq==0 writes
    ax2 += __shfl_xor_sync(0xffffffffu, ax2, 1);
    ax2 += __shfl_xor_sync(0xffffffffu, ax2, 2);
    by2 += __shfl_xor_sync(0xffffffffu, by2, 1);
    by2 += __shfl_xor_sync(0xffffffffu, by2, 2);
    if (lq == 0) {
        g_partX2[chunk * BSZ + lrow] = ax2;
        g_partY2[chunk * BSZ + lrow] = by2;
    }
}

// ---------------------------------------------------------------------------
// Stage B: deterministic reduction, 2-way chunk split per CTA.
// CTA i handles row i; thread (j, h) sums chunks [h*64, h*64+64).
// ---------------------------------------------------------------------------
__global__ __launch_bounds__(256, 4) void assemble_kernel()
{
    __shared__ float sS[2][BSZ];
    __shared__ float sY[2][BSZ];
    __shared__ float sX[2];

    const int i = blockIdx.x;
    const int j = threadIdx.x & 127;
    const int h = threadIdx.x >> 7;
    const int c0 = h * (NCHUNK / 2);

    float s = 0.f, x2 = 0.f, y2 = 0.f;
#pragma unroll 8
    for (int c = 0; c < NCHUNK / 2; c++) {
        s  += g_partC[(size_t)(c0 + c) * BSZ * BSZ + i * BSZ + j];
        x2 += g_partX2[(c0 + c) * BSZ + i];
        y2 += g_partY2[(c0 + c) * BSZ + j];
    }
    sS[h][j] = s;
    sY[h][j] = y2;
    if (j == 0) sX[h] = x2;
    __syncthreads();
    if (h == 0) {
        const float st = s + sS[1][j];
        const float yt = y2 + sY[1][j];
        const float xt = sX[0] + sX[1];
        const float sq = fmaxf(xt + yt - 2.0f * st, 0.0f);
        g_C[i * BSZ + j] = sqrtf(sq);
    }
}

// ---------------------------------------------------------------------------
// Stage C: Sinkhorn (100 iters), ONE CTA of 512 threads (128-reg budget: no
// spills). Thread group of 4 lanes owns one row (phase 1) / col (phase 2),
// 32 register-resident P/Q elements each. w vectors read as float4 from smem.
// ---------------------------------------------------------------------------
__global__ __launch_bounds__(512, 1) void sinkhorn_kernel(float* __restrict__ out)
{
    __shared__ __align__(16) float w_s[BSZ];    // exp(-v_j)
    __shared__ __align__(16) float wu_s[BSZ];   // exp(-u_i)
    __shared__ float u_fin[BSZ];
    __shared__ float v_fin[BSZ];

    const int t = threadIdx.x;
    const int r4 = t >> 2;        // row/col id 0..127
    const int g = t & 3;          // 4 lanes cooperate
    const int off = g << 5;       // 32-element segment

    float p[32], q[32];
    float M_i, N_j;

    {
        float m = -3.0e38f;
#pragma unroll
        for (int k = 0; k < 32; k++) {
            p[k] = g_C[r4 * BSZ + off + k];
            m = fmaxf(m, p[k]);
        }
        m = fmaxf(m, __shfl_xor_sync(0xffffffffu, m, 1));
        m = fmaxf(m, __shfl_xor_sync(0xffffffffu, m, 2));
        M_i = m;
#pragma unroll
        for (int k = 0; k < 32; k++) p[k] = __expf(p[k] - m);
    }
    {
        float n = -3.0e38f;
#pragma unroll
        for (int k = 0; k < 32; k++) {
            q[k] = g_C[(off + k) * BSZ + r4];
            n = fmaxf(n, q[k]);
        }
        n = fmaxf(n, __shfl_xor_sync(0xffffffffu, n, 1));
        n = fmaxf(n, __shfl_xor_sync(0xffffffffu, n, 2));
        N_j = n;
#pragma unroll
        for (int k = 0; k < 32; k++) q[k] = __expf(q[k] - n);
    }

    float u_i = 0.0f, v_j = 0.0f;
    if (t < BSZ) { w_s[t] = 1.0f; wu_s[t] = 1.0f; }   // u0 = v0 = 0
    __syncthreads();

    const float4* w4  = (const float4*)(w_s  + off);
    const float4* wu4 = (const float4*)(wu_s + off);

    for (int it = 0; it < 100; it++) {
        // ---- phase 1: u update ----
        float s0 = 0.f, s1 = 0.f, s2 = 0.f, s3 = 0.f;
#pragma unroll
        for (int k4 = 0; k4 < 8; k4++) {
            const float4 w = w4[k4];
            s0 = fmaf(p[k4 * 4 + 0], w.x, s0);
            s1 = fmaf(p[k4 * 4 + 1], w.y, s1);
            s2 = fmaf(p[k4 * 4 + 2], w.z, s2);
            s3 = fmaf(p[k4 * 4 + 3], w.w, s3);
        }
        float s = (s0 + s1) + (s2 + s3);
        s += __shfl_xor_sync(0xffffffffu, s, 1);
        s += __shfl_xor_sync(0xffffffffu, s, 2);
        if (g == 0) {
            u_i = REGC * (LOGAB + u_i - M_i - __logf(s));
            wu_s[r4] = __expf(-u_i);
        }
        __syncthreads();

        // ---- phase 2: v update ----
        float t0 = 0.f, t1 = 0.f, t2 = 0.f, t3 = 0.f;
#pragma unroll
        for (int k4 = 0; k4 < 8; k4++) {
            const float4 w = wu4[k4];
            t0 = fmaf(q[k4 * 4 + 0], w.x, t0);
            t1 = fmaf(q[k4 * 4 + 1], w.y, t1);
            t2 = fmaf(q[k4 * 4 + 2], w.z, t2);
            t3 = fmaf(q[k4 * 4 + 3], w.w, t3);
        }
        float tt = (t0 + t1) + (t2 + t3);
        tt += __shfl_xor_sync(0xffffffffu, tt, 1);
        tt += __shfl_xor_sync(0xffffffffu, tt, 2);
        if (g == 0) {
            v_j = REGC * (LOGAB + v_j - N_j - __logf(tt));
            w_s[r4] = __expf(-v_j);
        }
        __syncthreads();
    }

    if (g == 0) { u_fin[r4] = u_i; v_fin[r4] = v_j; }
    __syncthreads();
    if (t == 0) {
        float acc = 0.0f;
        for (int i = 0; i < BSZ; i++) acc += u_fin[i] + v_fin[i];
        out[0] = acc * (1.0f / 128.0f);   // sum(u*a + v*b), a=b=1/128
    }
}

// ---------------------------------------------------------------------------
extern "C" void kernel_launch(void* const* d_in, const int* in_sizes, int n_in,
                              void* d_out, int out_size)
{
    const float* imgs  = (const float*)d_in[0];
    const float* imgsw = (const float*)d_in[1];
    const float* tgt   = (const float*)d_in[2];

    gemm_part_kernel<<<NCHUNK, 512>>>(imgs, imgsw, tgt);
    assemble_kernel<<<BSZ, 256>>>();
    sinkhorn_kernel<<<1, 512>>>((float*)d_out);
}

// round 9
// speedup vs baseline: 2.9931x; 1.6561x over previous
#include <cuda_runtime.h>
#include <cuda_bf16.h>
#include <cstdint>

#define BSZ 128
#define KTOT 196608
#define NCHUNK 128
#define KC 1536           // NCHUNK * KC == KTOT
#define KT 32             // k per smem stage
#define NST (KC / KT)     // 48 stages
#define SA 40             // smem row stride in bf16 (KT + 8 pad)
#define REGC 0.01f
#define LOGAB -4.852030263919617f   // log(1/128)

// Scratch (static device arrays: no allocation anywhere)
__device__ float g_partC[(size_t)NCHUNK * BSZ * BSZ];   // 8 MB partial GEMM sums
__device__ float g_partX2[NCHUNK * BSZ];
__device__ float g_partY2[NCHUNK * BSZ];
__device__ float g_C[BSZ * BSZ];

// mma.sync m16n8k16 bf16 -> f32, accumulate in place
__device__ __forceinline__ void mma_bf16(float* c,
                                         uint32_t a0, uint32_t a1, uint32_t a2, uint32_t a3,
                                         uint32_t b0, uint32_t b1)
{
    asm volatile(
        "mma.sync.aligned.m16n8k16.row.col.f32.bf16.bf16.f32 "
        "{%0,%1,%2,%3}, {%4,%5,%6,%7}, {%8,%9}, {%0,%1,%2,%3};\n"
        : "+f"(c[0]), "+f"(c[1]), "+f"(c[2]), "+f"(c[3])
        : "r"(a0), "r"(a1), "r"(a2), "r"(a3), "r"(b0), "r"(b1));
}

// ---------------------------------------------------------------------------
// Stage A: split-K partial GEMM, bf16 HMMA, 2-stage double-buffered pipeline.
// (unchanged from R6: 87us measured)
// ---------------------------------------------------------------------------
__global__ __launch_bounds__(512, 1) void gemm_part_kernel(
    const float* __restrict__ imgs,
    const float* __restrict__ imgsw,
    const float* __restrict__ tgt)
{
    __shared__ __nv_bfloat16 As[2][BSZ][SA];
    __shared__ __nv_bfloat16 Bs[2][BSZ][SA];

    const int chunk = blockIdx.x;
    const int k0 = chunk * KC;
    const int t = threadIdx.x;
    const int warp = t >> 5;
    const int lane = t & 31;
    const int gid = lane >> 2;        // 0..7
    const int tig = lane & 3;         // 0..3
    const int wr = warp & 3;          // warp row block (32 rows)
    const int wc = warp >> 2;         // warp col block (32 cols)

    const int lrow = t >> 2;          // 0..127
    const int lq = t & 3;

    float c[2][4][4];
#pragma unroll
    for (int i = 0; i < 2; i++)
#pragma unroll
        for (int j = 0; j < 4; j++)
#pragma unroll
            for (int r = 0; r < 4; r++) c[i][j][r] = 0.0f;

    float ax2 = 0.0f, by2 = 0.0f;

    float4 raw[2], ra0[2], rbb[2];    // prefetch registers (6 float4)

    auto load_stage = [&](int s) {
        const size_t base = (size_t)lrow * KTOT + (size_t)(k0 + s * KT);
#pragma unroll
        for (int i = 0; i < 2; i++) {
            const int kk = (lq + 4 * i) * 4;
            raw[i] = *(const float4*)(imgsw + base + kk);
            ra0[i] = *(const float4*)(imgs  + base + kk);
            rbb[i] = *(const float4*)(tgt   + base + kk);
        }
    };

    auto convert_stage = [&](int buf) {
#pragma unroll
        for (int i = 0; i < 2; i++) {
            const int kk = (lq + 4 * i) * 4;
            const float d0 = raw[i].x - ra0[i].x;
            const float d1 = raw[i].y - ra0[i].y;
            const float d2 = raw[i].z - ra0[i].z;
            const float d3 = raw[i].w - ra0[i].w;
            ax2 += d0 * d0 + d1 * d1 + d2 * d2 + d3 * d3;
            by2 += rbb[i].x * rbb[i].x + rbb[i].y * rbb[i].y
                 + rbb[i].z * rbb[i].z + rbb[i].w * rbb[i].w;
            *(__nv_bfloat162*)&As[buf][lrow][kk + 0] = __floats2bfloat162_rn(d0, d1);
            *(__nv_bfloat162*)&As[buf][lrow][kk + 2] = __floats2bfloat162_rn(d2, d3);
            *(__nv_bfloat162*)&Bs[buf][lrow][kk + 0] = __floats2bfloat162_rn(rbb[i].x, rbb[i].y);
            *(__nv_bfloat162*)&Bs[buf][lrow][kk + 2] = __floats2bfloat162_rn(rbb[i].z, rbb[i].w);
        }
    };

    auto mma_stage = [&](int buf) {
#pragma unroll
        for (int ks = 0; ks < KT / 16; ks++) {
            const int kb = ks * 16;
            uint32_t af[2][4];
#pragma unroll
            for (int i = 0; i < 2; i++) {
                const int r0 = wr * 32 + i * 16 + gid;
                af[i][0] = *(const uint32_t*)&As[buf][r0    ][kb + 2 * tig    ];
                af[i][1] = *(const uint32_t*)&As[buf][r0 + 8][kb + 2 * tig    ];
                af[i][2] = *(const uint32_t*)&As[buf][r0    ][kb + 2 * tig + 8];
                af[i][3] = *(const uint32_t*)&As[buf][r0 + 8][kb + 2 * tig + 8];
            }
            uint32_t bfr[4][2];
#pragma unroll
            for (int j = 0; j < 4; j++) {
                const int col = wc * 32 + j * 8 + gid;
                bfr[j][0] = *(const uint32_t*)&Bs[buf][col][kb + 2 * tig    ];
                bfr[j][1] = *(const uint32_t*)&Bs[buf][col][kb + 2 * tig + 8];
            }
#pragma unroll
            for (int i = 0; i < 2; i++)
#pragma unroll
                for (int j = 0; j < 4; j++)
                    mma_bf16(c[i][j], af[i][0], af[i][1], af[i][2], af[i][3],
                             bfr[j][0], bfr[j][1]);
        }
    };

    load_stage(0);
    convert_stage(0);
    __syncthreads();
    for (int s = 0; s < NST; s++) {
        if (s + 1 < NST) load_stage(s + 1);
        mma_stage(s & 1);
        if (s + 1 < NST) convert_stage((s + 1) & 1);
        __syncthreads();
    }

    float* outp = &g_partC[(size_t)chunk * BSZ * BSZ];
#pragma unroll
    for (int i = 0; i < 2; i++) {
        const int r0 = wr * 32 + i * 16 + gid;
#pragma unroll
        for (int j = 0; j < 4; j++) {
            const int col = wc * 32 + j * 8 + 2 * tig;
            *(float2*)&outp[r0 * BSZ + col]       = make_float2(c[i][j][0], c[i][j][1]);
            *(float2*)&outp[(r0 + 8) * BSZ + col] = make_float2(c[i][j][2], c[i][j][3]);
        }
    }

    ax2 += __shfl_xor_sync(0xffffffffu, ax2, 1);
    ax2 += __shfl_xor_sync(0xffffffffu, ax2, 2);
    by2 += __shfl_xor_sync(0xffffffffu, by2, 1);
    by2 += __shfl_xor_sync(0xffffffffu, by2, 2);
    if (lq == 0) {
        g_partX2[chunk * BSZ + lrow] = ax2;
        g_partY2[chunk * BSZ + lrow] = by2;
    }
}

// ---------------------------------------------------------------------------
// Stage B: deterministic reduction, 2-way chunk split per CTA. (unchanged)
// ---------------------------------------------------------------------------
__global__ __launch_bounds__(256, 4) void assemble_kernel()
{
    __shared__ float sS[2][BSZ];
    __shared__ float sY[2][BSZ];
    __shared__ float sX[2];

    const int i = blockIdx.x;
    const int j = threadIdx.x & 127;
    const int h = threadIdx.x >> 7;
    const int c0 = h * (NCHUNK / 2);

    float s = 0.f, x2 = 0.f, y2 = 0.f;
#pragma unroll 8
    for (int c = 0; c < NCHUNK / 2; c++) {
        s  += g_partC[(size_t)(c0 + c) * BSZ * BSZ + i * BSZ + j];
        x2 += g_partX2[(c0 + c) * BSZ + i];
        y2 += g_partY2[(c0 + c) * BSZ + j];
    }
    sS[h][j] = s;
    sY[h][j] = y2;
    if (j == 0) sX[h] = x2;
    __syncthreads();
    if (h == 0) {
        const float st = s + sS[1][j];
        const float yt = y2 + sY[1][j];
        const float xt = sX[0] + sX[1];
        const float sq = fmaxf(xt + yt - 2.0f * st, 0.0f);
        g_C[i * BSZ + j] = sqrtf(sq);
    }
}

// ---------------------------------------------------------------------------
// Stage C: Sinkhorn (100 iters), ONE CTA of 256 threads.
// 255-reg cap at 256 threads: p[64]+q[64]=128 array regs + ~32 overhead fit
// with large headroom -> NO register spill (the R1/R6 killer).
// 2 lanes per row/col; 8 accumulators keep the FMA chain depth at 8.
// ---------------------------------------------------------------------------
__global__ __launch_bounds__(256, 1) void sinkhorn_kernel(float* __restrict__ out)
{
    __shared__ __align__(16) float w_s[BSZ];    // exp(-v_j)
    __shared__ __align__(16) float wu_s[BSZ];   // exp(-u_i)
    __shared__ float u_fin[BSZ];
    __shared__ float v_fin[BSZ];

    const int t = threadIdx.x;
    const int r2 = t >> 1;        // row (phase 1) / col (phase 2), 0..127
    const int g = t & 1;          // 2 lanes cooperate
    const int off = g << 6;       // 64-element segment

    float p[64], q[64];
    float M_i, N_j;

    {
        float m = -3.0e38f;
#pragma unroll 4
        for (int k = 0; k < 64; k++) {
            p[k] = g_C[r2 * BSZ + off + k];
            m = fmaxf(m, p[k]);
        }
        m = fmaxf(m, __shfl_xor_sync(0xffffffffu, m, 1));
        M_i = m;
#pragma unroll 4
        for (int k = 0; k < 64; k++) p[k] = __expf(p[k] - m);
    }
    {
        float n = -3.0e38f;
#pragma unroll 4
        for (int k = 0; k < 64; k++) {
            q[k] = g_C[(off + k) * BSZ + r2];
            n = fmaxf(n, q[k]);
        }
        n = fmaxf(n, __shfl_xor_sync(0xffffffffu, n, 1));
        N_j = n;
#pragma unroll 4
        for (int k = 0; k < 64; k++) q[k] = __expf(q[k] - n);
    }

    float u_i = 0.0f, v_j = 0.0f;
    if (t < BSZ) { w_s[t] = 1.0f; wu_s[t] = 1.0f; }   // u0 = v0 = 0
    __syncthreads();

    const float4* w4  = (const float4*)(w_s  + off);
    const float4* wu4 = (const float4*)(wu_s + off);

    for (int it = 0; it < 100; it++) {
        // ---- phase 1: u update ----
        float a0 = 0.f, a1 = 0.f, a2 = 0.f, a3 = 0.f;
        float a4 = 0.f, a5 = 0.f, a6 = 0.f, a7 = 0.f;
#pragma unroll
        for (int k4 = 0; k4 < 16; k4 += 2) {
            const float4 wA = w4[k4];
            const float4 wB = w4[k4 + 1];
            a0 = fmaf(p[k4 * 4 + 0], wA.x, a0);
            a1 = fmaf(p[k4 * 4 + 1], wA.y, a1);
            a2 = fmaf(p[k4 * 4 + 2], wA.z, a2);
            a3 = fmaf(p[k4 * 4 + 3], wA.w, a3);
            a4 = fmaf(p[k4 * 4 + 4], wB.x, a4);
            a5 = fmaf(p[k4 * 4 + 5], wB.y, a5);
            a6 = fmaf(p[k4 * 4 + 6], wB.z, a6);
            a7 = fmaf(p[k4 * 4 + 7], wB.w, a7);
        }
        float s = ((a0 + a1) + (a2 + a3)) + ((a4 + a5) + (a6 + a7));
        s += __shfl_xor_sync(0xffffffffu, s, 1);
        if (g == 0) {
            u_i = REGC * (LOGAB + u_i - M_i - __logf(s));
            wu_s[r2] = __expf(-u_i);
        }
        __syncthreads();

        // ---- phase 2: v update ----
        float b0 = 0.f, b1 = 0.f, b2 = 0.f, b3 = 0.f;
        float b4 = 0.f, b5 = 0.f, b6 = 0.f, b7 = 0.f;
#pragma unroll
        for (int k4 = 0; k4 < 16; k4 += 2) {
            const float4 wA = wu4[k4];
            const float4 wB = wu4[k4 + 1];
            b0 = fmaf(q[k4 * 4 + 0], wA.x, b0);
            b1 = fmaf(q[k4 * 4 + 1], wA.y, b1);
            b2 = fmaf(q[k4 * 4 + 2], wA.z, b2);
            b3 = fmaf(q[k4 * 4 + 3], wA.w, b3);
            b4 = fmaf(q[k4 * 4 + 4], wB.x, b4);
            b5 = fmaf(q[k4 * 4 + 5], wB.y, b5);
            b6 = fmaf(q[k4 * 4 + 6], wB.z, b6);
            b7 = fmaf(q[k4 * 4 + 7], wB.w, b7);
        }
        float tt = ((b0 + b1) + (b2 + b3)) + ((b4 + b5) + (b6 + b7));
        tt += __shfl_xor_sync(0xffffffffu, tt, 1);
        if (g == 0) {
            v_j = REGC * (LOGAB + v_j - N_j - __logf(tt));
            w_s[r2] = __expf(-v_j);
        }
        __syncthreads();
    }

    if (g == 0) { u_fin[r2] = u_i; v_fin[r2] = v_j; }
    __syncthreads();
    // parallel final reduction in warp 0
    if (t < 32) {
        float acc = 0.0f;
#pragma unroll
        for (int i = 0; i < 4; i++)
            acc += u_fin[t + 32 * i] + v_fin[t + 32 * i];
        acc += __shfl_xor_sync(0xffffffffu, acc, 16);
        acc += __shfl_xor_sync(0xffffffffu, acc, 8);
        acc += __shfl_xor_sync(0xffffffffu, acc, 4);
        acc += __shfl_xor_sync(0xffffffffu, acc, 2);
        acc += __shfl_xor_sync(0xffffffffu, acc, 1);
        if (t == 0) out[0] = acc * (1.0f / 128.0f);   // sum(u*a + v*b), a=b=1/128
    }
}

// ---------------------------------------------------------------------------
extern "C" void kernel_launch(void* const* d_in, const int* in_sizes, int n_in,
                              void* d_out, int out_size)
{
    const float* imgs  = (const float*)d_in[0];
    const float* imgsw = (const float*)d_in[1];
    const float* tgt   = (const float*)d_in[2];

    gemm_part_kernel<<<NCHUNK, 512>>>(imgs, imgsw, tgt);
    assemble_kernel<<<BSZ, 256>>>();
    sinkhorn_kernel<<<1, 256>>>((float*)d_out);
}

// round 11
// speedup vs baseline: 3.7045x; 1.2377x over previous
#include <cuda_runtime.h>
#include <cuda_bf16.h>
#include <cstdint>

#define BSZ 128
#define KTOT 196608
#define NCHUNK 128
#define KC 1536           // NCHUNK * KC == KTOT
#define KT 32             // k floats per stage
#define NST (KC / KT)     // 48 stages
#define NBUF 3            // raw staging depth
#define RAWP 36           // raw row stride in floats (32 + 4 pad -> conflict-free)
#define SA 40             // bf16 tile row stride (KT + 8 pad)
#define REGC 0.01f
#define LOGAB -4.852030263919617f   // log(1/128)

typedef unsigned long long u64;

// Scratch (static device arrays: no allocation anywhere)
__device__ float g_partC[(size_t)NCHUNK * BSZ * BSZ];   // 8 MB partial GEMM sums
__device__ float g_partX2[NCHUNK * BSZ];
__device__ float g_partY2[NCHUNK * BSZ];
__device__ float g_C[BSZ * BSZ];

// ---- PTX helpers -----------------------------------------------------------
__device__ __forceinline__ void mma_bf16(float* c,
                                         uint32_t a0, uint32_t a1, uint32_t a2, uint32_t a3,
                                         uint32_t b0, uint32_t b1)
{
    asm volatile(
        "mma.sync.aligned.m16n8k16.row.col.f32.bf16.bf16.f32 "
        "{%0,%1,%2,%3}, {%4,%5,%6,%7}, {%8,%9}, {%0,%1,%2,%3};\n"
        : "+f"(c[0]), "+f"(c[1]), "+f"(c[2]), "+f"(c[3])
        : "r"(a0), "r"(a1), "r"(a2), "r"(a3), "r"(b0), "r"(b1));
}

__device__ __forceinline__ uint32_t cvta_s(const void* p) {
    uint32_t a;
    asm("{ .reg .u64 t; cvta.to.shared.u64 t, %1; cvt.u32.u64 %0, t; }" : "=r"(a) : "l"(p));
    return a;
}
__device__ __forceinline__ void cp16(uint32_t saddr, const void* g) {
    asm volatile("cp.async.cg.shared.global [%0], [%1], 16;\n" :: "r"(saddr), "l"(g));
}
__device__ __forceinline__ void cp_commit() { asm volatile("cp.async.commit_group;\n"); }
template <int N> __device__ __forceinline__ void cp_wait() {
    asm volatile("cp.async.wait_group %0;\n" :: "n"(N));
}
__device__ __forceinline__ void fma2(u64& acc, u64 a, u64 b) {
    asm("fma.rn.f32x2 %0, %1, %2, %0;" : "+l"(acc) : "l"(a), "l"(b));
}
__device__ __forceinline__ u64 pack2(float lo, float hi) {
    u64 r; asm("mov.b64 %0, {%1,%2};" : "=l"(r) : "f"(lo), "f"(hi)); return r;
}
__device__ __forceinline__ float2 unpack2(u64 v) {
    float lo, hi; asm("mov.b64 {%0,%1}, %2;" : "=f"(lo), "=f"(hi) : "l"(v));
    return make_float2(lo, hi);
}
__device__ __forceinline__ uint32_t bf2_as_u32(__nv_bfloat162 v) {
    __nv_bfloat162_raw r = *(__nv_bfloat162_raw*)&v;
    return (uint32_t)r.x | ((uint32_t)r.y << 16);
}

// ---------------------------------------------------------------------------
// Stage A: split-K partial GEMM, bf16 HMMA, cp.async 3-deep raw staging.
// 512 threads / 16 warps, warp tile 32x32 (2x4 m16n8k16 tiles).
// Raw fp32 staged gmem->smem by LDGSTS (no per-stage gmem latency exposure);
// each raw address is written+read by exactly ONE thread -> no raw barriers.
// ---------------------------------------------------------------------------
#define RAW_ARR (NBUF * BSZ * RAWP)          // floats per raw array
#define SMEM_GEMM_BYTES ((3 * RAW_ARR) * 4 + 2 * 2 * BSZ * SA * 2)

__global__ __launch_bounds__(512, 1) void gemm_part_kernel(
    const float* __restrict__ imgs,
    const float* __restrict__ imgsw,
    const float* __restrict__ tgt)
{
    extern __shared__ float smem[];
    float* rawW = smem;                      // [NBUF][BSZ][RAWP]
    float* rawI = rawW + RAW_ARR;
    float* rawT = rawI + RAW_ARR;
    __nv_bfloat16* As = (__nv_bfloat16*)(rawT + RAW_ARR);   // [2][BSZ][SA]
    __nv_bfloat16* Bs = As + 2 * BSZ * SA;

    const int chunk = blockIdx.x;
    const int k0 = chunk * KC;
    const int t = threadIdx.x;
    const int warp = t >> 5;
    const int lane = t & 31;
    const int gid = lane >> 2;        // 0..7
    const int tig = lane & 3;         // 0..3
    const int wr = warp & 3;          // warp row block (32 rows)
    const int wc = warp >> 2;         // warp col block (32 cols)

    // Loader: 8 lanes per row; thread covers rows r0 and r0+64, 16B chunk lq
    const int r0 = t >> 3;            // 0..63
    const int r1 = r0 + 64;
    const int lq = t & 7;             // 16B chunk within 128B row

    const uint32_t sW = cvta_s(rawW);
    const uint32_t sI = cvta_s(rawI);
    const uint32_t sT = cvta_s(rawT);

    float c[2][4][4];
#pragma unroll
    for (int i = 0; i < 2; i++)
#pragma unroll
        for (int j = 0; j < 4; j++)
#pragma unroll
            for (int r = 0; r < 4; r++) c[i][j][r] = 0.0f;

    float ax2a = 0.f, ax2b = 0.f, by2a = 0.f, by2b = 0.f;

    auto cp_stage = [&](int st, int buf) {
        const size_t g0 = (size_t)r0 * KTOT + (size_t)(k0 + st * KT + lq * 4);
        const size_t g1 = (size_t)r1 * KTOT + (size_t)(k0 + st * KT + lq * 4);
        const uint32_t o0 = (uint32_t)(((buf * BSZ + r0) * RAWP + lq * 4) * 4);
        const uint32_t o1 = (uint32_t)(((buf * BSZ + r1) * RAWP + lq * 4) * 4);
        cp16(sW + o0, imgsw + g0); cp16(sW + o1, imgsw + g1);
        cp16(sI + o0, imgs  + g0); cp16(sI + o1, imgs  + g1);
        cp16(sT + o0, tgt   + g0); cp16(sT + o1, tgt   + g1);
        cp_commit();
    };

    auto convert_row = [&](int rb, int bb, int row, float& x2, float& y2) {
        const int ri = (rb * BSZ + row) * RAWP + lq * 4;
        const float4 w = *(const float4*)&rawW[ri];
        const float4 a = *(const float4*)&rawI[ri];
        const float4 b = *(const float4*)&rawT[ri];
        const float d0 = w.x - a.x, d1 = w.y - a.y, d2 = w.z - a.z, d3 = w.w - a.w;
        x2 += d0 * d0 + d1 * d1 + d2 * d2 + d3 * d3;
        y2 += b.x * b.x + b.y * b.y + b.z * b.z + b.w * b.w;
        uint2 da, db;
        da.x = bf2_as_u32(__floats2bfloat162_rn(d0, d1));
        da.y = bf2_as_u32(__floats2bfloat162_rn(d2, d3));
        db.x = bf2_as_u32(__floats2bfloat162_rn(b.x, b.y));
        db.y = bf2_as_u32(__floats2bfloat162_rn(b.z, b.w));
        *(uint2*)&As[(bb * BSZ + row) * SA + lq * 4] = da;
        *(uint2*)&Bs[(bb * BSZ + row) * SA + lq * 4] = db;
    };

    auto convert_stage = [&](int rb, int bb) {
        convert_row(rb, bb, r0, ax2a, by2a);
        convert_row(rb, bb, r1, ax2b, by2b);
    };

    auto mma_stage = [&](int bb) {
#pragma unroll
        for (int ks = 0; ks < KT / 16; ks++) {
            const int kb = ks * 16;
            uint32_t af[2][4];
#pragma unroll
            for (int i = 0; i < 2; i++) {
                const int rr = wr * 32 + i * 16 + gid;
                const __nv_bfloat16* pa = &As[(bb * BSZ + rr) * SA + kb + 2 * tig];
                af[i][0] = *(const uint32_t*)(pa);
                af[i][1] = *(const uint32_t*)(pa + 8 * SA);
                af[i][2] = *(const uint32_t*)(pa + 8);
                af[i][3] = *(const uint32_t*)(pa + 8 * SA + 8);
            }
            uint32_t bfr[4][2];
#pragma unroll
            for (int j = 0; j < 4; j++) {
                const int col = wc * 32 + j * 8 + gid;
                const __nv_bfloat16* pb = &Bs[(bb * BSZ + col) * SA + kb + 2 * tig];
                bfr[j][0] = *(const uint32_t*)(pb);
                bfr[j][1] = *(const uint32_t*)(pb + 8);
            }
#pragma unroll
            for (int i = 0; i < 2; i++)
#pragma unroll
                for (int j = 0; j < 4; j++)
                    mma_bf16(c[i][j], af[i][0], af[i][1], af[i][2], af[i][3],
                             bfr[j][0], bfr[j][1]);
        }
    };

    // prologue: fill 3 raw stages, convert stage 0
    cp_stage(0, 0);
    cp_stage(1, 1);
    cp_stage(2, 2);
    cp_wait<2>();
    convert_stage(0, 0);
    __syncthreads();

    for (int s = 0; s < NST; s++) {
        if (s + 3 < NST) cp_stage(s + 3, (s + 3) % NBUF);
        mma_stage(s & 1);
        if (s + 1 < NST) {
            const int rem = NST - 2 - s;   // groups committed after stage s+1
            if (rem >= 2)      cp_wait<2>();
            else if (rem == 1) cp_wait<1>();
            else               cp_wait<0>();
            convert_stage((s + 1) % NBUF, (s + 1) & 1);
        }
        __syncthreads();
    }

    // write partial C tile (deterministic, one writer per slot)
    float* outp = &g_partC[(size_t)chunk * BSZ * BSZ];
#pragma unroll
    for (int i = 0; i < 2; i++) {
        const int rr = wr * 32 + i * 16 + gid;
#pragma unroll
        for (int j = 0; j < 4; j++) {
            const int col = wc * 32 + j * 8 + 2 * tig;
            *(float2*)&outp[rr * BSZ + col]       = make_float2(c[i][j][0], c[i][j][1]);
            *(float2*)&outp[(rr + 8) * BSZ + col] = make_float2(c[i][j][2], c[i][j][3]);
        }
    }

    // norms: reduce over the 8 lanes (lq) that share each row
#pragma unroll
    for (int d = 1; d < 8; d <<= 1) {
        ax2a += __shfl_xor_sync(0xffffffffu, ax2a, d);
        ax2b += __shfl_xor_sync(0xffffffffu, ax2b, d);
        by2a += __shfl_xor_sync(0xffffffffu, by2a, d);
        by2b += __shfl_xor_sync(0xffffffffu, by2b, d);
    }
    if (lq == 0) {
        g_partX2[chunk * BSZ + r0] = ax2a;
        g_partX2[chunk * BSZ + r1] = ax2b;
        g_partY2[chunk * BSZ + r0] = by2a;
        g_partY2[chunk * BSZ + r1] = by2b;
    }
}

// ---------------------------------------------------------------------------
// Stage B: deterministic reduction, 2-way chunk split per CTA. (unchanged)
// ---------------------------------------------------------------------------
__global__ __launch_bounds__(256, 4) void assemble_kernel()
{
    __shared__ float sS[2][BSZ];
    __shared__ float sY[2][BSZ];
    __shared__ float sX[2];

    const int i = blockIdx.x;
    const int j = threadIdx.x & 127;
    const int h = threadIdx.x >> 7;
    const int c0 = h * (NCHUNK / 2);

    float s = 0.f, x2 = 0.f, y2 = 0.f;
#pragma unroll 8
    for (int c = 0; c < NCHUNK / 2; c++) {
        s  += g_partC[(size_t)(c0 + c) * BSZ * BSZ + i * BSZ + j];
        x2 += g_partX2[(c0 + c) * BSZ + i];
        y2 += g_partY2[(c0 + c) * BSZ + j];
    }
    sS[h][j] = s;
    sY[h][j] = y2;
    if (j == 0) sX[h] = x2;
    __syncthreads();
    if (h == 0) {
        const float st = s + sS[1][j];
        const float yt = y2 + sY[1][j];
        const float xt = sX[0] + sX[1];
        const float sq = fmaxf(xt + yt - 2.0f * st, 0.0f);
        g_C[i * BSZ + j] = sqrtf(sq);
    }
}

// ---------------------------------------------------------------------------
// Stage C: Sinkhorn (100 iters), ONE CTA of 256 threads, spill-free.
// P/Q kept as packed f32x2 pairs (u64); inner GEMV uses fma.rn.f32x2 (FFMA2):
// 32 FFMA2 + 16 LDS.128 per thread per phase (was 64 FFMA + 16 LDS.128).
// ---------------------------------------------------------------------------
__global__ __launch_bounds__(256, 1) void sinkhorn_kernel(float* __restrict__ out)
{
    __shared__ __align__(16) float w_s[BSZ];    // exp(-v_j)
    __shared__ __align__(16) float wu_s[BSZ];   // exp(-u_i)
    __shared__ float u_fin[BSZ];
    __shared__ float v_fin[BSZ];

    const int t = threadIdx.x;
    const int r2 = t >> 1;        // row (phase 1) / col (phase 2), 0..127
    const int g = t & 1;          // 2 lanes cooperate
    const int off = g << 6;       // 64-element segment

    u64 p2[32], q2[32];
    float M_i, N_j;

    {
        float m = -3.0e38f;
        float pv[64];
#pragma unroll 4
        for (int k = 0; k < 64; k++) {
            pv[k] = g_C[r2 * BSZ + off + k];
            m = fmaxf(m, pv[k]);
        }
        m = fmaxf(m, __shfl_xor_sync(0xffffffffu, m, 1));
        M_i = m;
#pragma unroll 4
        for (int k = 0; k < 32; k++)
            p2[k] = pack2(__expf(pv[2 * k] - m), __expf(pv[2 * k + 1] - m));
    }
    {
        float n = -3.0e38f;
        float qv[64];
#pragma unroll 4
        for (int k = 0; k < 64; k++) {
            qv[k] = g_C[(off + k) * BSZ + r2];
            n = fmaxf(n, qv[k]);
        }
        n = fmaxf(n, __shfl_xor_sync(0xffffffffu, n, 1));
        N_j = n;
#pragma unroll 4
        for (int k = 0; k < 32; k++)
            q2[k] = pack2(__expf(qv[2 * k] - n), __expf(qv[2 * k + 1] - n));
    }

    float u_i = 0.0f, v_j = 0.0f;
    if (t < BSZ) { w_s[t] = 1.0f; wu_s[t] = 1.0f; }   // u0 = v0 = 0
    __syncthreads();

    const ulonglong2* w22  = (const ulonglong2*)(w_s  + off);
    const ulonglong2* wu22 = (const ulonglong2*)(wu_s + off);

    for (int it = 0; it < 100; it++) {
        // ---- phase 1: u update ----
        u64 a0 = 0ull, a1 = 0ull, a2 = 0ull, a3 = 0ull;
#pragma unroll
        for (int k = 0; k < 16; k += 2) {
            const ulonglong2 wA = w22[k];
            const ulonglong2 wB = w22[k + 1];
            fma2(a0, p2[2 * k + 0], wA.x);
            fma2(a1, p2[2 * k + 1], wA.y);
            fma2(a2, p2[2 * k + 2], wB.x);
            fma2(a3, p2[2 * k + 3], wB.y);
        }
        const float2 f0 = unpack2(a0), f1 = unpack2(a1);
        const float2 f2 = unpack2(a2), f3 = unpack2(a3);
        float s = ((f0.x + f0.y) + (f1.x + f1.y)) + ((f2.x + f2.y) + (f3.x + f3.y));
        s += __shfl_xor_sync(0xffffffffu, s, 1);
        if (g == 0) {
            u_i = REGC * (LOGAB + u_i - M_i - __logf(s));
            wu_s[r2] = __expf(-u_i);
        }
        __syncthreads();

        // ---- phase 2: v update ----
        u64 b0 = 0ull, b1 = 0ull, b2 = 0ull, b3 = 0ull;
#pragma unroll
        for (int k = 0; k < 16; k += 2) {
            const ulonglong2 wA = wu22[k];
            const ulonglong2 wB = wu22[k + 1];
            fma2(b0, q2[2 * k + 0], wA.x);
            fma2(b1, q2[2 * k + 1], wA.y);
            fma2(b2, q2[2 * k + 2], wB.x);
            fma2(b3, q2[2 * k + 3], wB.y);
        }
        const float2 h0 = unpack2(b0), h1 = unpack2(b1);
        const float2 h2 = unpack2(b2), h3 = unpack2(b3);
        float tt = ((h0.x + h0.y) + (h1.x + h1.y)) + ((h2.x + h2.y) + (h3.x + h3.y));
        tt += __shfl_xor_sync(0xffffffffu, tt, 1);
        if (g == 0) {
            v_j = REGC * (LOGAB + v_j - N_j - __logf(tt));
            w_s[r2] = __expf(-v_j);
        }
        __syncthreads();
    }

    if (g == 0) { u_fin[r2] = u_i; v_fin[r2] = v_j; }
    __syncthreads();
    if (t < 32) {
        float acc = 0.0f;
#pragma unroll
        for (int i = 0; i < 4; i++)
            acc += u_fin[t + 32 * i] + v_fin[t + 32 * i];
        acc += __shfl_xor_sync(0xffffffffu, acc, 16);
        acc += __shfl_xor_sync(0xffffffffu, acc, 8);
        acc += __shfl_xor_sync(0xffffffffu, acc, 4);
        acc += __shfl_xor_sync(0xffffffffu, acc, 2);
        acc += __shfl_xor_sync(0xffffffffu, acc, 1);
        if (t == 0) out[0] = acc * (1.0f / 128.0f);   // sum(u*a + v*b), a=b=1/128
    }
}

// ---------------------------------------------------------------------------
extern "C" void kernel_launch(void* const* d_in, const int* in_sizes, int n_in,
                              void* d_out, int out_size)
{
    const float* imgs  = (const float*)d_in[0];
    const float* imgsw = (const float*)d_in[1];
    const float* tgt   = (const float*)d_in[2];

    static int smem_set = 0;
    if (!smem_set) {
        cudaFuncSetAttribute(gemm_part_kernel,
                             cudaFuncAttributeMaxDynamicSharedMemorySize,
                             SMEM_GEMM_BYTES);
        smem_set = 1;
    }

    gemm_part_kernel<<<NCHUNK, 512, SMEM_GEMM_BYTES>>>(imgs, imgsw, tgt);
    assemble_kernel<<<BSZ, 256>>>();
    sinkhorn_kernel<<<1, 256>>>((float*)d_out);
}

// round 12
// speedup vs baseline: 4.1419x; 1.1181x over previous
#include <cuda_runtime.h>
#include <cuda_bf16.h>
#include <cstdint>

#define BSZ 128
#define KTOT 196608
#define NCHUNK 148        // one CTA per SM
#define NSTG_TOT 6144     // KTOT / KT
#define KT 32             // k floats per stage
#define NBUF 3            // raw staging depth
#define RAWP 36           // raw row stride in floats (32 + 4 pad -> conflict-free)
#define SA 40             // bf16 tile row stride (KT + 8 pad)
#define REGC 0.01f
#define LOGAB -4.852030263919617f   // log(1/128)
#define WDUP 196          // g-lane base offset into duplicated w arrays (bank-disjoint)

typedef unsigned long long u64;

// Scratch (static device arrays: no allocation anywhere)
__device__ float g_partC[(size_t)NCHUNK * BSZ * BSZ];
__device__ float g_partX2[NCHUNK * BSZ];
__device__ float g_partY2[NCHUNK * BSZ];
__device__ float g_C[BSZ * BSZ];

// ---- PTX helpers -----------------------------------------------------------
__device__ __forceinline__ void mma_bf16(float* c,
                                         uint32_t a0, uint32_t a1, uint32_t a2, uint32_t a3,
                                         uint32_t b0, uint32_t b1)
{
    asm volatile(
        "mma.sync.aligned.m16n8k16.row.col.f32.bf16.bf16.f32 "
        "{%0,%1,%2,%3}, {%4,%5,%6,%7}, {%8,%9}, {%0,%1,%2,%3};\n"
        : "+f"(c[0]), "+f"(c[1]), "+f"(c[2]), "+f"(c[3])
        : "r"(a0), "r"(a1), "r"(a2), "r"(a3), "r"(b0), "r"(b1));
}

__device__ __forceinline__ uint32_t cvta_s(const void* p) {
    uint32_t a;
    asm("{ .reg .u64 t; cvta.to.shared.u64 t, %1; cvt.u32.u64 %0, t; }" : "=r"(a) : "l"(p));
    return a;
}
__device__ __forceinline__ void cp16(uint32_t saddr, const void* g) {
    asm volatile("cp.async.cg.shared.global [%0], [%1], 16;\n" :: "r"(saddr), "l"(g));
}
__device__ __forceinline__ void cp_commit() { asm volatile("cp.async.commit_group;\n"); }
template <int N> __device__ __forceinline__ void cp_wait() {
    asm volatile("cp.async.wait_group %0;\n" :: "n"(N));
}
__device__ __forceinline__ void fma2(u64& acc, u64 a, u64 b) {
    asm("fma.rn.f32x2 %0, %1, %2, %0;" : "+l"(acc) : "l"(a), "l"(b));
}
__device__ __forceinline__ u64 pack2(float lo, float hi) {
    u64 r; asm("mov.b64 %0, {%1,%2};" : "=l"(r) : "f"(lo), "f"(hi)); return r;
}
__device__ __forceinline__ float2 unpack2(u64 v) {
    float lo, hi; asm("mov.b64 {%0,%1}, %2;" : "=f"(lo), "=f"(hi) : "l"(v));
    return make_float2(lo, hi);
}
__device__ __forceinline__ uint32_t bf2_as_u32(__nv_bfloat162 v) {
    __nv_bfloat162_raw r = *(__nv_bfloat162_raw*)&v;
    return (uint32_t)r.x | ((uint32_t)r.y << 16);
}

// ---------------------------------------------------------------------------
// Stage A: split-K partial GEMM, bf16 HMMA, cp.async 3-deep raw staging.
// Grid = 148 (one CTA per SM); uneven stage split covers all 6144 stages.
// ---------------------------------------------------------------------------
#define RAW_ARR (NBUF * BSZ * RAWP)
#define SMEM_GEMM_BYTES ((3 * RAW_ARR) * 4 + 2 * 2 * BSZ * SA * 2)

__global__ __launch_bounds__(512, 1) void gemm_part_kernel(
    const float* __restrict__ imgs,
    const float* __restrict__ imgsw,
    const float* __restrict__ tgt)
{
    extern __shared__ float smem[];
    float* rawW = smem;                      // [NBUF][BSZ][RAWP]
    float* rawI = rawW + RAW_ARR;
    float* rawT = rawI + RAW_ARR;
    __nv_bfloat16* As = (__nv_bfloat16*)(rawT + RAW_ARR);   // [2][BSZ][SA]
    __nv_bfloat16* Bs = As + 2 * BSZ * SA;

    const int chunk = blockIdx.x;
    const int st0 = (chunk * NSTG_TOT) / NCHUNK;
    const int st1 = ((chunk + 1) * NSTG_TOT) / NCHUNK;
    const int nst = st1 - st0;               // 41 or 42 stages
    const int k0 = st0 * KT;

    const int t = threadIdx.x;
    const int warp = t >> 5;
    const int lane = t & 31;
    const int gid = lane >> 2;
    const int tig = lane & 3;
    const int wr = warp & 3;
    const int wc = warp >> 2;

    const int r0 = t >> 3;            // 0..63
    const int r1 = r0 + 64;
    const int lq = t & 7;

    const uint32_t sW = cvta_s(rawW);
    const uint32_t sI = cvta_s(rawI);
    const uint32_t sT = cvta_s(rawT);

    float c[2][4][4];
#pragma unroll
    for (int i = 0; i < 2; i++)
#pragma unroll
        for (int j = 0; j < 4; j++)
#pragma unroll
            for (int r = 0; r < 4; r++) c[i][j][r] = 0.0f;

    float ax2a = 0.f, ax2b = 0.f, by2a = 0.f, by2b = 0.f;

    auto cp_stage = [&](int st, int buf) {
        const size_t g0 = (size_t)r0 * KTOT + (size_t)(k0 + st * KT + lq * 4);
        const size_t g1 = (size_t)r1 * KTOT + (size_t)(k0 + st * KT + lq * 4);
        const uint32_t o0 = (uint32_t)(((buf * BSZ + r0) * RAWP + lq * 4) * 4);
        const uint32_t o1 = (uint32_t)(((buf * BSZ + r1) * RAWP + lq * 4) * 4);
        cp16(sW + o0, imgsw + g0); cp16(sW + o1, imgsw + g1);
        cp16(sI + o0, imgs  + g0); cp16(sI + o1, imgs  + g1);
        cp16(sT + o0, tgt   + g0); cp16(sT + o1, tgt   + g1);
        cp_commit();
    };

    auto convert_row = [&](int rb, int bb, int row, float& x2, float& y2) {
        const int ri = (rb * BSZ + row) * RAWP + lq * 4;
        const float4 w = *(const float4*)&rawW[ri];
        const float4 a = *(const float4*)&rawI[ri];
        const float4 b = *(const float4*)&rawT[ri];
        const float d0 = w.x - a.x, d1 = w.y - a.y, d2 = w.z - a.z, d3 = w.w - a.w;
        x2 += d0 * d0 + d1 * d1 + d2 * d2 + d3 * d3;
        y2 += b.x * b.x + b.y * b.y + b.z * b.z + b.w * b.w;
        uint2 da, db;
        da.x = bf2_as_u32(__floats2bfloat162_rn(d0, d1));
        da.y = bf2_as_u32(__floats2bfloat162_rn(d2, d3));
        db.x = bf2_as_u32(__floats2bfloat162_rn(b.x, b.y));
        db.y = bf2_as_u32(__floats2bfloat162_rn(b.z, b.w));
        *(uint2*)&As[(bb * BSZ + row) * SA + lq * 4] = da;
        *(uint2*)&Bs[(bb * BSZ + row) * SA + lq * 4] = db;
    };

    auto convert_stage = [&](int rb, int bb) {
        convert_row(rb, bb, r0, ax2a, by2a);
        convert_row(rb, bb, r1, ax2b, by2b);
    };

    auto mma_stage = [&](int bb) {
#pragma unroll
        for (int ks = 0; ks < KT / 16; ks++) {
            const int kb = ks * 16;
            uint32_t af[2][4];
#pragma unroll
            for (int i = 0; i < 2; i++) {
                const int rr = wr * 32 + i * 16 + gid;
                const __nv_bfloat16* pa = &As[(bb * BSZ + rr) * SA + kb + 2 * tig];
                af[i][0] = *(const uint32_t*)(pa);
                af[i][1] = *(const uint32_t*)(pa + 8 * SA);
                af[i][2] = *(const uint32_t*)(pa + 8);
                af[i][3] = *(const uint32_t*)(pa + 8 * SA + 8);
            }
            uint32_t bfr[4][2];
#pragma unroll
            for (int j = 0; j < 4; j++) {
                const int col = wc * 32 + j * 8 + gid;
                const __nv_bfloat16* pb = &Bs[(bb * BSZ + col) * SA + kb + 2 * tig];
                bfr[j][0] = *(const uint32_t*)(pb);
                bfr[j][1] = *(const uint32_t*)(pb + 8);
            }
#pragma unroll
            for (int i = 0; i < 2; i++)
#pragma unroll
                for (int j = 0; j < 4; j++)
                    mma_bf16(c[i][j], af[i][0], af[i][1], af[i][2], af[i][3],
                             bfr[j][0], bfr[j][1]);
        }
    };

    // prologue (nst >= 41, so 3 stages always exist)
    cp_stage(0, 0);
    cp_stage(1, 1);
    cp_stage(2, 2);
    cp_wait<2>();
    convert_stage(0, 0);
    __syncthreads();

    for (int s = 0; s < nst; s++) {
        if (s + 3 < nst) cp_stage(s + 3, (s + 3) % NBUF);
        mma_stage(s & 1);
        if (s + 1 < nst) {
            const int rem = nst - 2 - s;   // groups committed after stage s+1
            if (rem >= 2)      cp_wait<2>();
            else if (rem == 1) cp_wait<1>();
            else               cp_wait<0>();
            convert_stage((s + 1) % NBUF, (s + 1) & 1);
        }
        __syncthreads();
    }

    // write partial C tile (deterministic, one writer per slot)
    float* outp = &g_partC[(size_t)chunk * BSZ * BSZ];
#pragma unroll
    for (int i = 0; i < 2; i++) {
        const int rr = wr * 32 + i * 16 + gid;
#pragma unroll
        for (int j = 0; j < 4; j++) {
            const int col = wc * 32 + j * 8 + 2 * tig;
            *(float2*)&outp[rr * BSZ + col]       = make_float2(c[i][j][0], c[i][j][1]);
            *(float2*)&outp[(rr + 8) * BSZ + col] = make_float2(c[i][j][2], c[i][j][3]);
        }
    }

    // norms: reduce over the 8 lanes (lq) that share each row
#pragma unroll
    for (int d = 1; d < 8; d <<= 1) {
        ax2a += __shfl_xor_sync(0xffffffffu, ax2a, d);
        ax2b += __shfl_xor_sync(0xffffffffu, ax2b, d);
        by2a += __shfl_xor_sync(0xffffffffu, by2a, d);
        by2b += __shfl_xor_sync(0xffffffffu, by2b, d);
    }
    if (lq == 0) {
        g_partX2[chunk * BSZ + r0] = ax2a;
        g_partX2[chunk * BSZ + r1] = ax2b;
        g_partY2[chunk * BSZ + r0] = by2a;
        g_partY2[chunk * BSZ + r1] = by2b;
    }
}

// ---------------------------------------------------------------------------
// Stage B: deterministic reduction, 2-way chunk split per CTA (74 + 74).
// ---------------------------------------------------------------------------
__global__ __launch_bounds__(256, 4) void assemble_kernel()
{
    __shared__ float sS[2][BSZ];
    __shared__ float sY[2][BSZ];
    __shared__ float sX[2];

    const int i = blockIdx.x;
    const int j = threadIdx.x & 127;
    const int h = threadIdx.x >> 7;
    const int c0 = h * (NCHUNK / 2);

    float s = 0.f, x2 = 0.f, y2 = 0.f;
#pragma unroll 2
    for (int c = 0; c < NCHUNK / 2; c++) {
        s  += g_partC[(size_t)(c0 + c) * BSZ * BSZ + i * BSZ + j];
        x2 += g_partX2[(c0 + c) * BSZ + i];
        y2 += g_partY2[(c0 + c) * BSZ + j];
    }
    sS[h][j] = s;
    sY[h][j] = y2;
    if (j == 0) sX[h] = x2;
    __syncthreads();
    if (h == 0) {
        const float st = s + sS[1][j];
        const float yt = y2 + sY[1][j];
        const float xt = sX[0] + sX[1];
        const float sq = fmaxf(xt + yt - 2.0f * st, 0.0f);
        g_C[i * BSZ + j] = sqrtf(sq);
    }
}

// ---------------------------------------------------------------------------
// Stage C: Sinkhorn (100 iters), ONE CTA of 256 threads, spill-free, FFMA2.
// w vectors kept in TWO smem copies 132 floats apart: g=0 lanes read copy A
// (banks 4k..4k+3), g=1 lanes read copy B at idx 196+4k (banks 4k+4..4k+7).
// The two broadcast addresses per LDS.128 now hit DISJOINT banks
// -> 1 wavefront per instruction (was 2): smem cost per phase halves.
// ---------------------------------------------------------------------------
__global__ __launch_bounds__(256, 1) void sinkhorn_kernel(float* __restrict__ out)
{
    __shared__ __align__(16) float wv[264];    // exp(-v): copies at 0 and 132
    __shared__ __align__(16) float wu[264];    // exp(-u): copies at 0 and 132
    __shared__ float u_fin[BSZ];
    __shared__ float v_fin[BSZ];

    const int t = threadIdx.x;
    const int r2 = t >> 1;        // row (phase 1) / col (phase 2), 0..127
    const int g = t & 1;          // 2 lanes cooperate
    const int off = g << 6;       // 64-element segment

    u64 p2[32], q2[32];
    float M_i, N_j;

    {
        float m = -3.0e38f;
        float pv[64];
#pragma unroll 4
        for (int k = 0; k < 64; k++) {
            pv[k] = g_C[r2 * BSZ + off + k];
            m = fmaxf(m, pv[k]);
        }
        m = fmaxf(m, __shfl_xor_sync(0xffffffffu, m, 1));
        M_i = m;
#pragma unroll 4
        for (int k = 0; k < 32; k++)
            p2[k] = pack2(__expf(pv[2 * k] - m), __expf(pv[2 * k + 1] - m));
    }
    {
        float n = -3.0e38f;
        float qv[64];
#pragma unroll 4
        for (int k = 0; k < 64; k++) {
            qv[k] = g_C[(off + k) * BSZ + r2];
            n = fmaxf(n, qv[k]);
        }
        n = fmaxf(n, __shfl_xor_sync(0xffffffffu, n, 1));
        N_j = n;
#pragma unroll 4
        for (int k = 0; k < 32; k++)
            q2[k] = pack2(__expf(qv[2 * k] - n), __expf(qv[2 * k + 1] - n));
    }

    float u_i = 0.0f, v_j = 0.0f;
    if (t < BSZ) {                // u0 = v0 = 0 -> both copies = 1
        wv[t] = 1.0f; wv[132 + t] = 1.0f;
        wu[t] = 1.0f; wu[132 + t] = 1.0f;
    }
    __syncthreads();

    // g=0 reads copy A at float idx off(=0); g=1 reads copy B at idx 132+64=196
    const ulonglong2* w22  = (const ulonglong2*)(wv + g * WDUP);
    const ulonglong2* wu22 = (const ulonglong2*)(wu + g * WDUP);

    for (int it = 0; it < 100; it++) {
        // ---- phase 1: u update ----
        u64 a0 = 0ull, a1 = 0ull, a2 = 0ull, a3 = 0ull;
#pragma unroll
        for (int k = 0; k < 16; k += 2) {
            const ulonglong2 wA = w22[k];
            const ulonglong2 wB = w22[k + 1];
            fma2(a0, p2[2 * k + 0], wA.x);
            fma2(a1, p2[2 * k + 1], wA.y);
            fma2(a2, p2[2 * k + 2], wB.x);
            fma2(a3, p2[2 * k + 3], wB.y);
        }
        const float2 f0 = unpack2(a0), f1 = unpack2(a1);
        const float2 f2 = unpack2(a2), f3 = unpack2(a3);
        float s = ((f0.x + f0.y) + (f1.x + f1.y)) + ((f2.x + f2.y) + (f3.x + f3.y));
        s += __shfl_xor_sync(0xffffffffu, s, 1);
        if (g == 0) {
            u_i = REGC * (LOGAB + u_i - M_i - __logf(s));
            const float e = __expf(-u_i);
            wu[r2] = e; wu[132 + r2] = e;
        }
        __syncthreads();

        // ---- phase 2: v update ----
        u64 b0 = 0ull, b1 = 0ull, b2 = 0ull, b3 = 0ull;
#pragma unroll
        for (int k = 0; k < 16; k += 2) {
            const ulonglong2 wA = wu22[k];
            const ulonglong2 wB = wu22[k + 1];
            fma2(b0, q2[2 * k + 0], wA.x);
            fma2(b1, q2[2 * k + 1], wA.y);
            fma2(b2, q2[2 * k + 2], wB.x);
            fma2(b3, q2[2 * k + 3], wB.y);
        }
        const float2 h0 = unpack2(b0), h1 = unpack2(b1);
        const float2 h2 = unpack2(b2), h3 = unpack2(b3);
        float tt = ((h0.x + h0.y) + (h1.x + h1.y)) + ((h2.x + h2.y) + (h3.x + h3.y));
        tt += __shfl_xor_sync(0xffffffffu, tt, 1);
        if (g == 0) {
            v_j = REGC * (LOGAB + v_j - N_j - __logf(tt));
            const float e = __expf(-v_j);
            wv[r2] = e; wv[132 + r2] = e;
        }
        __syncthreads();
    }

    if (g == 0) { u_fin[r2] = u_i; v_fin[r2] = v_j; }
    __syncthreads();
    if (t < 32) {
        float acc = 0.0f;
#pragma unroll
        for (int i = 0; i < 4; i++)
            acc += u_fin[t + 32 * i] + v_fin[t + 32 * i];
        acc += __shfl_xor_sync(0xffffffffu, acc, 16);
        acc += __shfl_xor_sync(0xffffffffu, acc, 8);
        acc += __shfl_xor_sync(0xffffffffu, acc, 4);
        acc += __shfl_xor_sync(0xffffffffu, acc, 2);
        acc += __shfl_xor_sync(0xffffffffu, acc, 1);
        if (t == 0) out[0] = acc * (1.0f / 128.0f);   // sum(u*a + v*b), a=b=1/128
    }
}

// ---------------------------------------------------------------------------
extern "C" void kernel_launch(void* const* d_in, const int* in_sizes, int n_in,
                              void* d_out, int out_size)
{
    const float* imgs  = (const float*)d_in[0];
    const float* imgsw = (const float*)d_in[1];
    const float* tgt   = (const float*)d_in[2];

    static int smem_set = 0;
    if (!smem_set) {
        cudaFuncSetAttribute(gemm_part_kernel,
                             cudaFuncAttributeMaxDynamicSharedMemorySize,
                             SMEM_GEMM_BYTES);
        smem_set = 1;
    }

    gemm_part_kernel<<<NCHUNK, 512, SMEM_GEMM_BYTES>>>(imgs, imgsw, tgt);
    assemble_kernel<<<BSZ, 256>>>();
    sinkhorn_kernel<<<1, 256>>>((float*)d_out);
}